// round 3
// baseline (speedup 1.0000x reference)
#include <cuda_runtime.h>
#include <cstdint>
#include <cstddef>

// Problem shape (fixed by the dataset)
#define BB   8
#define CC   256
#define CQ   64
#define NSP  4096   // H*W = 64*64

// ---------------------------------------------------------------------------
// Scratch (static __device__ arrays -- no allocation allowed)
// ---------------------------------------------------------------------------
__device__ __align__(16) float g_Wall[384 * 256];            // [Wq;Wk;Wg@Wv] rows x 256, tf32-rounded
__device__ __align__(16) float g_ball[384];                  // [bq;bk;Wg@bv]
__device__ __align__(16) float g_qT[BB * NSP * CQ];          // [b][i][c]  tf32-rounded
__device__ __align__(16) float g_kT[BB * NSP * CQ];          // [b][j][c]  tf32-rounded
__device__ __align__(16) float g_Vp[BB * CC * NSP];          // [b][o][n]  tf32-rounded (= Wg@V)

// ---------------------------------------------------------------------------
// Helpers
// ---------------------------------------------------------------------------
__device__ __forceinline__ float rna_tf32(float x) {
    unsigned y;
    asm("cvt.rna.tf32.f32 %0, %1;" : "=r"(y) : "f"(x));
    return __uint_as_float(y);
}

__device__ __forceinline__ void mma8(float* d, const unsigned* a, unsigned b0, unsigned b1) {
    asm volatile(
        "mma.sync.aligned.m16n8k8.row.col.f32.tf32.tf32.f32 "
        "{%0,%1,%2,%3}, {%4,%5,%6,%7}, {%8,%9}, {%0,%1,%2,%3};"
        : "+f"(d[0]), "+f"(d[1]), "+f"(d[2]), "+f"(d[3])
        : "r"(a[0]), "r"(a[1]), "r"(a[2]), "r"(a[3]), "r"(b0), "r"(b1));
}

// ---------------------------------------------------------------------------
// Kernel 0: fold gamma into value conv. Wall rows: [0,64)=Wq, [64,128)=Wk,
// [128,384)=Wg@Wv. ball likewise (b' = Wg@bv).
// ---------------------------------------------------------------------------
__global__ void prep_weights(const float* __restrict__ Wq, const float* __restrict__ bq,
                             const float* __restrict__ Wk, const float* __restrict__ bk,
                             const float* __restrict__ Wv, const float* __restrict__ bv,
                             const float* __restrict__ Wg) {
    const int r = blockIdx.x;
    const int t = threadIdx.x;
    if (r < 64) {
        g_Wall[r * 256 + t] = rna_tf32(Wq[r * 256 + t]);
        if (t == 0) g_ball[r] = bq[r];
    } else if (r < 128) {
        g_Wall[r * 256 + t] = rna_tf32(Wk[(r - 64) * 256 + t]);
        if (t == 0) g_ball[r] = bk[r - 64];
    } else {
        const int o = r - 128;
        __shared__ float wg[256];
        wg[t] = Wg[o * 256 + t];
        __syncthreads();
        float acc = 0.f;
#pragma unroll 8
        for (int c = 0; c < 256; c++) acc = fmaf(wg[c], Wv[c * 256 + t], acc);
        g_Wall[r * 256 + t] = rna_tf32(acc);
        if (t == 0) {
            float bacc = 0.f;
            for (int c = 0; c < 256; c++) bacc = fmaf(wg[c], bv[c], bacc);
            g_ball[r] = bacc;
        }
    }
}

// ---------------------------------------------------------------------------
// Kernel 1: Out[384 x N] = Wall @ x[b]  (+ball), per batch. TF32 mma.
// Writes qT/kT (i-major, Cq contiguous) and Vp (o-major, n contiguous).
// grid (3, 32, 8): 128 rows x 128 spatial per CTA, 256 threads.
// ---------------------------------------------------------------------------
__device__ __forceinline__ void store_qkv(int b, int r, int i, float v) {
    v = rna_tf32(v + g_ball[r]);
    if (r < 64)        g_qT[((size_t)b * NSP + i) * CQ + r] = v;
    else if (r < 128)  g_kT[((size_t)b * NSP + i) * CQ + (r - 64)] = v;
    else               g_Vp[((size_t)b * CC + (r - 128)) * NSP + i] = v;
}

__global__ __launch_bounds__(256) void qkv_kernel(const float* __restrict__ x) {
    __shared__ float xs[32][136];   // [c-slice][i]  pitch 136 -> conflict-free B frags
    __shared__ float ws[128][36];   // [row][c-slice] pitch 36 -> conflict-free A frags
    const int b  = blockIdx.z;
    const int r0 = blockIdx.x * 128;
    const int i0 = blockIdx.y * 128;
    const int tid = threadIdx.x;
    const int w = tid >> 5, l = tid & 31, g = l >> 2, t = l & 3;
    const int rw = (w & 3) * 32;      // warp row base within 128
    const int iw = (w >> 2) * 64;     // warp spatial base within 128

    float oacc[2][8][4];
#pragma unroll
    for (int a = 0; a < 2; a++)
#pragma unroll
        for (int j = 0; j < 8; j++)
#pragma unroll
            for (int e = 0; e < 4; e++) oacc[a][j][e] = 0.f;

    const float* xb = x + (size_t)b * CC * NSP;

    for (int kc = 0; kc < 256; kc += 32) {
        __syncthreads();
#pragma unroll
        for (int u = tid; u < 1024; u += 256) {       // xs: 32 x 128 floats
            int c = u >> 5, i4 = (u & 31) * 4;
            float4 v = *(const float4*)(xb + (size_t)(kc + c) * NSP + i0 + i4);
            xs[c][i4 + 0] = rna_tf32(v.x);
            xs[c][i4 + 1] = rna_tf32(v.y);
            xs[c][i4 + 2] = rna_tf32(v.z);
            xs[c][i4 + 3] = rna_tf32(v.w);
        }
#pragma unroll
        for (int u = tid; u < 1024; u += 256) {       // ws: 128 x 32 floats (pre-rounded)
            int r = u >> 3, c4 = (u & 7) * 4;
            *(float4*)&ws[r][c4] = *(const float4*)(g_Wall + (r0 + r) * 256 + kc + c4);
        }
        __syncthreads();
#pragma unroll
        for (int kk = 0; kk < 32; kk += 8) {
            unsigned a[2][4];
#pragma unroll
            for (int mt = 0; mt < 2; mt++) {
                const int rb = rw + mt * 16;
                a[mt][0] = __float_as_uint(ws[rb + g][kk + t]);
                a[mt][1] = __float_as_uint(ws[rb + g + 8][kk + t]);
                a[mt][2] = __float_as_uint(ws[rb + g][kk + t + 4]);
                a[mt][3] = __float_as_uint(ws[rb + g + 8][kk + t + 4]);
            }
#pragma unroll
            for (int jt = 0; jt < 8; jt++) {
                unsigned b0 = __float_as_uint(xs[kk + t][iw + jt * 8 + g]);
                unsigned b1 = __float_as_uint(xs[kk + t + 4][iw + jt * 8 + g]);
                mma8(oacc[0][jt], a[0], b0, b1);
                mma8(oacc[1][jt], a[1], b0, b1);
            }
        }
    }

#pragma unroll
    for (int mt = 0; mt < 2; mt++) {
#pragma unroll
        for (int jt = 0; jt < 8; jt++) {
            const int rlo = r0 + rw + mt * 16 + g;
            const int rhi = rlo + 8;
            const int ib  = i0 + iw + jt * 8 + 2 * t;
            store_qkv(b, rlo, ib,     oacc[mt][jt][0]);
            store_qkv(b, rlo, ib + 1, oacc[mt][jt][1]);
            store_qkv(b, rhi, ib,     oacc[mt][jt][2]);
            store_qkv(b, rhi, ib + 1, oacc[mt][jt][3]);
        }
    }
}

// ---------------------------------------------------------------------------
// Kernel 2: fused attention. Per CTA: 128 output columns (m), all 256 rows.
//   loop n-tiles of 64: S[64x128] = qT[n,:] @ kT[m,:]^T ; S = elu(S)/N
//                       O[256x128] += Vp[:, n] @ S
// Epilogue adds gamma bias and writes final output directly.
// grid (32, 8), 512 threads, 153 KB dynamic smem.
// ---------------------------------------------------------------------------
#define SM2_FLOATS ((128 + 64 + 128 + 256) * 68)
#define SM2_BYTES  (SM2_FLOATS * 4)

__device__ __forceinline__ float elu_scale(float v) {
    float e = (v > 0.f) ? v : expm1f(v);
    return rna_tf32(e * (1.0f / 4096.0f));
}

__global__ __launch_bounds__(512) void attn_kernel(float* __restrict__ out,
                                                   const float* __restrict__ bg) {
    extern __shared__ float sm[];
    float (*ks)[68] = (float(*)[68])(sm);                       // [m 128][c 64]
    float (*qs)[68] = (float(*)[68])(sm + 128 * 68);            // [i 64][c 64]
    float (*ss)[68] = (float(*)[68])(sm + (128 + 64) * 68);     // [m 128][n 64] (= S^T)
    float (*vs)[68] = (float(*)[68])(sm + (128 + 64 + 128) * 68); // [o 256][n 64]

    const int b  = blockIdx.y;
    const int m0 = blockIdx.x * 128;
    const int tid = threadIdx.x;
    const int w = tid >> 5, l = tid & 31, g = l >> 2, t = l & 3;
    // GEMM1 warp tile: 16(i) x 32(j)
    const int i1 = (w & 3) * 16;
    const int j1 = (w >> 2) * 32;
    // GEMM2 warp tile: 32(o) x 64(m)
    const int c2 = (w & 7) * 32;
    const int j2 = (w >> 3) * 64;

    const float* kTb = g_kT + ((size_t)b * NSP + m0) * CQ;
    const float* qTb = g_qT + (size_t)b * NSP * CQ;
    const float* Vb  = g_Vp + (size_t)b * CC * NSP;

    // K tile resident for whole CTA
#pragma unroll
    for (int u = tid; u < 128 * 16; u += 512) {
        int j = u >> 4, c4 = (u & 15) * 4;
        *(float4*)&ks[j][c4] = *(const float4*)(kTb + j * CQ + c4);
    }

    float oacc[2][8][4];
#pragma unroll
    for (int a = 0; a < 2; a++)
#pragma unroll
        for (int j = 0; j < 8; j++)
#pragma unroll
            for (int e = 0; e < 4; e++) oacc[a][j][e] = 0.f;

    for (int n0 = 0; n0 < NSP; n0 += 64) {
        __syncthreads();   // prior GEMM2 done with vs/ss; prior GEMM1 done with qs
#pragma unroll
        for (int u = tid; u < 64 * 16; u += 512) {     // qs: 64 x 64
            int i = u >> 4, c4 = (u & 15) * 4;
            *(float4*)&qs[i][c4] = *(const float4*)(qTb + (size_t)(n0 + i) * CQ + c4);
        }
#pragma unroll
        for (int u = tid; u < 256 * 16; u += 512) {    // vs: 256 x 64
            int c = u >> 4, n4 = (u & 15) * 4;
            *(float4*)&vs[c][n4] = *(const float4*)(Vb + (size_t)c * NSP + n0 + n4);
        }
        __syncthreads();

        // ---- GEMM1: S = q^T k ----
        float sacc[4][4];
#pragma unroll
        for (int j = 0; j < 4; j++)
#pragma unroll
            for (int e = 0; e < 4; e++) sacc[j][e] = 0.f;

#pragma unroll
        for (int kk = 0; kk < 64; kk += 8) {
            unsigned a[4];
            a[0] = __float_as_uint(qs[i1 + g][kk + t]);
            a[1] = __float_as_uint(qs[i1 + g + 8][kk + t]);
            a[2] = __float_as_uint(qs[i1 + g][kk + t + 4]);
            a[3] = __float_as_uint(qs[i1 + g + 8][kk + t + 4]);
#pragma unroll
            for (int jt = 0; jt < 4; jt++) {
                unsigned b0 = __float_as_uint(ks[j1 + jt * 8 + g][kk + t]);
                unsigned b1 = __float_as_uint(ks[j1 + jt * 8 + g][kk + t + 4]);
                mma8(sacc[jt], a, b0, b1);
            }
        }

        // ---- elu/N epilogue -> ss (transposed: ss[m][n]) ----
#pragma unroll
        for (int jt = 0; jt < 4; jt++) {
            const int ma  = j1 + jt * 8 + 2 * t;
            const int ilo = i1 + g, ihi = ilo + 8;
            ss[ma    ][ilo] = elu_scale(sacc[jt][0]);
            ss[ma + 1][ilo] = elu_scale(sacc[jt][1]);
            ss[ma    ][ihi] = elu_scale(sacc[jt][2]);
            ss[ma + 1][ihi] = elu_scale(sacc[jt][3]);
        }
        __syncthreads();

        // ---- GEMM2: O += V' @ S ----
#pragma unroll
        for (int kk = 0; kk < 64; kk += 8) {
            unsigned a[2][4];
#pragma unroll
            for (int mt = 0; mt < 2; mt++) {
                const int cb = c2 + mt * 16;
                a[mt][0] = __float_as_uint(vs[cb + g][kk + t]);
                a[mt][1] = __float_as_uint(vs[cb + g + 8][kk + t]);
                a[mt][2] = __float_as_uint(vs[cb + g][kk + t + 4]);
                a[mt][3] = __float_as_uint(vs[cb + g + 8][kk + t + 4]);
            }
#pragma unroll
            for (int jt = 0; jt < 8; jt++) {
                unsigned b0 = __float_as_uint(ss[j2 + jt * 8 + g][kk + t]);
                unsigned b1 = __float_as_uint(ss[j2 + jt * 8 + g][kk + t + 4]);
                mma8(oacc[0][jt], a[0], b0, b1);
                mma8(oacc[1][jt], a[1], b0, b1);
            }
        }
    }

    // ---- final epilogue: add gamma bias, write output ----
#pragma unroll
    for (int mt = 0; mt < 2; mt++) {
        const int olo = c2 + mt * 16 + g;
        const int ohi = olo + 8;
        const float blo = __ldg(bg + olo);
        const float bhi = __ldg(bg + ohi);
#pragma unroll
        for (int jt = 0; jt < 8; jt++) {
            const int m_ = m0 + j2 + jt * 8 + 2 * t;
            float2 v0 = make_float2(oacc[mt][jt][0] + blo, oacc[mt][jt][1] + blo);
            float2 v1 = make_float2(oacc[mt][jt][2] + bhi, oacc[mt][jt][3] + bhi);
            *(float2*)(out + ((size_t)b * CC + olo) * NSP + m_) = v0;
            *(float2*)(out + ((size_t)b * CC + ohi) * NSP + m_) = v1;
        }
    }
}

// ---------------------------------------------------------------------------
// Launch
// ---------------------------------------------------------------------------
extern "C" void kernel_launch(void* const* d_in, const int* in_sizes, int n_in,
                              void* d_out, int out_size) {
    const float* x  = (const float*)d_in[0];
    const float* Wq = (const float*)d_in[1];
    const float* bq = (const float*)d_in[2];
    const float* Wk = (const float*)d_in[3];
    const float* bk = (const float*)d_in[4];
    const float* Wv = (const float*)d_in[5];
    const float* bv = (const float*)d_in[6];
    const float* Wg = (const float*)d_in[7];
    const float* bg = (const float*)d_in[8];
    float* out = (float*)d_out;

    // Not a stream op; idempotent and legal during graph capture.
    cudaFuncSetAttribute(attn_kernel, cudaFuncAttributeMaxDynamicSharedMemorySize, SM2_BYTES);

    prep_weights<<<384, 256>>>(Wq, bq, Wk, bk, Wv, bv, Wg);
    qkv_kernel<<<dim3(3, 32, 8), 256>>>(x);
    attn_kernel<<<dim3(32, 8), 512, SM2_BYTES>>>(out, bg);
}

// round 14
// speedup vs baseline: 1.2554x; 1.2554x over previous
#include <cuda_runtime.h>
#include <cstdint>
#include <cstddef>

// Problem shape (fixed by the dataset)
#define BB   8
#define CC   256
#define CQ   64
#define NSP  4096   // H*W = 64*64

// ---------------------------------------------------------------------------
// Scratch (static __device__ arrays -- no allocation allowed)
// ---------------------------------------------------------------------------
__device__ __align__(16) float g_Wall[384 * 256];            // [Wq;Wk;Wg@Wv]
__device__ __align__(16) float g_ball[384];                  // [bq;bk;Wg@bv]
__device__ __align__(16) float g_qT[BB * NSP * CQ];          // [b][i][c]  tf32-rounded
__device__ __align__(16) float g_kT[BB * NSP * CQ];          // [b][j][c]  tf32-rounded
__device__ __align__(16) float g_Vp[BB * CC * NSP];          // [b][o][n]  tf32-rounded

// ---------------------------------------------------------------------------
// Helpers
// ---------------------------------------------------------------------------
__device__ __forceinline__ float rna_tf32(float x) {
    unsigned y;
    asm("cvt.rna.tf32.f32 %0, %1;" : "=r"(y) : "f"(x));
    return __uint_as_float(y);
}

__device__ __forceinline__ uint32_t smem_u32(const void* p) {
    uint32_t a;
    asm("{ .reg .u64 t; cvta.to.shared.u64 t, %1; cvt.u32.u64 %0, t; }" : "=r"(a) : "l"(p));
    return a;
}

__device__ __forceinline__ void mma8(float* d, const unsigned* a, unsigned b0, unsigned b1) {
    asm volatile(
        "mma.sync.aligned.m16n8k8.row.col.f32.tf32.tf32.f32 "
        "{%0,%1,%2,%3}, {%4,%5,%6,%7}, {%8,%9}, {%0,%1,%2,%3};"
        : "+f"(d[0]), "+f"(d[1]), "+f"(d[2]), "+f"(d[3])
        : "r"(a[0]), "r"(a[1]), "r"(a[2]), "r"(a[3]), "r"(b0), "r"(b1));
}

__device__ __forceinline__ void cp16(uint32_t dst, const void* src) {
    asm volatile("cp.async.cg.shared.global [%0], [%1], 16;" :: "r"(dst), "l"(src) : "memory");
}
#define CP_COMMIT() asm volatile("cp.async.commit_group;" ::: "memory")
#define CP_WAIT1()  asm volatile("cp.async.wait_group 1;" ::: "memory")
#define CP_WAIT0()  asm volatile("cp.async.wait_group 0;" ::: "memory")

// ---------------------------------------------------------------------------
// Kernel 0: fold gamma into value conv. Blocks 0..31: round/copy Wq,Wk rows
// (4 rows each). Blocks 32..95: Wg@Wv, 4 output rows per block (Wv reuse x4).
// ---------------------------------------------------------------------------
__global__ __launch_bounds__(256) void prep_weights(
        const float* __restrict__ Wq, const float* __restrict__ bq,
        const float* __restrict__ Wk, const float* __restrict__ bk,
        const float* __restrict__ Wv, const float* __restrict__ bv,
        const float* __restrict__ Wg) {
    const int blk = blockIdx.x;
    const int t = threadIdx.x;
    if (blk < 32) {
#pragma unroll
        for (int rr = 0; rr < 4; rr++) {
            const int r = blk * 4 + rr;   // 0..127
            const float src = (r < 64) ? Wq[r * 256 + t] : Wk[(r - 64) * 256 + t];
            g_Wall[r * 256 + t] = rna_tf32(src);
        }
        if (t < 4) {
            const int r = blk * 4 + t;
            g_ball[r] = (r < 64) ? bq[r] : bk[r - 64];
        }
    } else {
        const int o0 = (blk - 32) * 4;    // 0..252
        __shared__ float wg[4][256];
#pragma unroll
        for (int rr = 0; rr < 4; rr++) wg[rr][t] = Wg[(o0 + rr) * 256 + t];
        __syncthreads();
        float acc0 = 0.f, acc1 = 0.f, acc2 = 0.f, acc3 = 0.f;
#pragma unroll 4
        for (int c = 0; c < 256; c++) {
            const float wv = Wv[c * 256 + t];
            acc0 = fmaf(wg[0][c], wv, acc0);
            acc1 = fmaf(wg[1][c], wv, acc1);
            acc2 = fmaf(wg[2][c], wv, acc2);
            acc3 = fmaf(wg[3][c], wv, acc3);
        }
        g_Wall[(128 + o0 + 0) * 256 + t] = rna_tf32(acc0);
        g_Wall[(128 + o0 + 1) * 256 + t] = rna_tf32(acc1);
        g_Wall[(128 + o0 + 2) * 256 + t] = rna_tf32(acc2);
        g_Wall[(128 + o0 + 3) * 256 + t] = rna_tf32(acc3);
        if (t < 4) {
            float bacc = 0.f;
            for (int c = 0; c < 256; c++) bacc = fmaf(wg[t][c], bv[c], bacc);
            g_ball[128 + o0 + t] = bacc;
        }
    }
}

// ---------------------------------------------------------------------------
// Kernel 1: qkv projection (mma.sync tf32 -- known good from R2)
// ---------------------------------------------------------------------------
__device__ __forceinline__ void store_qkv(int b, int r, int i, float v) {
    v = rna_tf32(v + g_ball[r]);
    if (r < 64)        g_qT[((size_t)b * NSP + i) * CQ + r] = v;
    else if (r < 128)  g_kT[((size_t)b * NSP + i) * CQ + (r - 64)] = v;
    else               g_Vp[((size_t)b * CC + (r - 128)) * NSP + i] = v;
}

__global__ __launch_bounds__(256) void qkv_kernel(const float* __restrict__ x) {
    __shared__ float xs[32][136];
    __shared__ float ws[128][36];
    const int b  = blockIdx.z;
    const int r0 = blockIdx.x * 128;
    const int i0 = blockIdx.y * 128;
    const int tid = threadIdx.x;
    const int w = tid >> 5, l = tid & 31, g = l >> 2, t = l & 3;
    const int rw = (w & 3) * 32;
    const int iw = (w >> 2) * 64;

    float oacc[2][8][4];
#pragma unroll
    for (int a = 0; a < 2; a++)
#pragma unroll
        for (int j = 0; j < 8; j++)
#pragma unroll
            for (int e = 0; e < 4; e++) oacc[a][j][e] = 0.f;

    const float* xb = x + (size_t)b * CC * NSP;

    for (int kc = 0; kc < 256; kc += 32) {
        __syncthreads();
#pragma unroll
        for (int u = tid; u < 1024; u += 256) {
            int c = u >> 5, i4 = (u & 31) * 4;
            float4 v = *(const float4*)(xb + (size_t)(kc + c) * NSP + i0 + i4);
            xs[c][i4 + 0] = rna_tf32(v.x);
            xs[c][i4 + 1] = rna_tf32(v.y);
            xs[c][i4 + 2] = rna_tf32(v.z);
            xs[c][i4 + 3] = rna_tf32(v.w);
        }
#pragma unroll
        for (int u = tid; u < 1024; u += 256) {
            int r = u >> 3, c4 = (u & 7) * 4;
            *(float4*)&ws[r][c4] = *(const float4*)(g_Wall + (r0 + r) * 256 + kc + c4);
        }
        __syncthreads();
#pragma unroll
        for (int kk = 0; kk < 32; kk += 8) {
            unsigned a[2][4];
#pragma unroll
            for (int mt = 0; mt < 2; mt++) {
                const int rb = rw + mt * 16;
                a[mt][0] = __float_as_uint(ws[rb + g][kk + t]);
                a[mt][1] = __float_as_uint(ws[rb + g + 8][kk + t]);
                a[mt][2] = __float_as_uint(ws[rb + g][kk + t + 4]);
                a[mt][3] = __float_as_uint(ws[rb + g + 8][kk + t + 4]);
            }
#pragma unroll
            for (int jt = 0; jt < 8; jt++) {
                unsigned b0 = __float_as_uint(xs[kk + t][iw + jt * 8 + g]);
                unsigned b1 = __float_as_uint(xs[kk + t + 4][iw + jt * 8 + g]);
                mma8(oacc[0][jt], a[0], b0, b1);
                mma8(oacc[1][jt], a[1], b0, b1);
            }
        }
    }

#pragma unroll
    for (int mt = 0; mt < 2; mt++) {
#pragma unroll
        for (int jt = 0; jt < 8; jt++) {
            const int rlo = r0 + rw + mt * 16 + g;
            const int rhi = rlo + 8;
            const int ib  = i0 + iw + jt * 8 + 2 * t;
            store_qkv(b, rlo, ib,     oacc[mt][jt][0]);
            store_qkv(b, rlo, ib + 1, oacc[mt][jt][1]);
            store_qkv(b, rhi, ib,     oacc[mt][jt][2]);
            store_qkv(b, rhi, ib + 1, oacc[mt][jt][3]);
        }
    }
}

// ---------------------------------------------------------------------------
// Kernel 2: fused attention (mma.sync tf32), cp.async-pipelined.
// Per CTA: batch b, 128 m-cols, all 256 c. Loop n-tiles of 64:
//   GEMM1: S[64n x 128m] = q.k ; elu/N -> ss[m][n] (transposed, pitch 68)
//   GEMM2: O[256c x 128m] += Vp[c][n] . ss
// V tiles double-buffered via cp.async; q tiles prefetched through registers;
// K tile CTA-resident. 3 barriers/iter; elu via MUFU (__expf).
// ---------------------------------------------------------------------------
#define ATT_KS   0                         // 128 x 68
#define ATT_QS   (128 * 68)                // 64 x 68
#define ATT_VS   (ATT_QS + 64 * 68)        // 2 x (256 x 68)
#define ATT_VSZ  (256 * 68)
#define ATT_SS   (ATT_VS + 2 * ATT_VSZ)    // 128 x 68
#define ATT_FLOATS (ATT_SS + 128 * 68)     // 56576
#define ATT_BYTES  (ATT_FLOATS * 4)        // 226304 <= 232448

__device__ __forceinline__ float elu_scale(float v) {
    float e = (v > 0.f) ? v : (__expf(v) - 1.0f);   // MUFU path, abs err ~1e-7
    return rna_tf32(e * (1.0f / 4096.0f));
}

__global__ __launch_bounds__(512, 1) void attn_kernel(float* __restrict__ out,
                                                      const float* __restrict__ bg) {
    extern __shared__ float sm[];
    float (*ks)[68] = (float(*)[68])(sm + ATT_KS);
    float (*qs)[68] = (float(*)[68])(sm + ATT_QS);
    float (*ss)[68] = (float(*)[68])(sm + ATT_SS);
    const uint32_t sb = smem_u32(sm);

    const int b  = blockIdx.y;
    const int m0 = blockIdx.x * 128;
    const int tid = threadIdx.x;
    const int w = tid >> 5, l = tid & 31, g = l >> 2, t4 = l & 3;
    // GEMM1 warp tile: 16(i=n) x 32(j=m); GEMM2 warp tile: 32(c) x 64(m)
    const int i1 = (w & 3) * 16;
    const int j1 = (w >> 2) * 32;
    const int c2 = (w & 7) * 32;
    const int j2 = (w >> 3) * 64;

    const float* kTb = g_kT + ((size_t)b * NSP + m0) * CQ;
    const float* qTb = g_qT + (size_t)b * NSP * CQ;
    const float* Vb  = g_Vp + (size_t)b * CC * NSP;

    // ---- prologue: cp.async K tile + V stage 0 (one group) ----
#pragma unroll
    for (int u = tid; u < 2048; u += 512) {          // ks 128 x 16 chunks
        int j = u >> 4, c4 = (u & 15) << 2;
        cp16(sb + (uint32_t)(ATT_KS + j * 68 + c4) * 4, kTb + j * CQ + c4);
    }
#pragma unroll
    for (int u = tid; u < 4096; u += 512) {          // vs0 256 x 16 chunks
        int c = u >> 4, n4 = (u & 15) << 2;
        cp16(sb + (uint32_t)(ATT_VS + c * 68 + n4) * 4, Vb + (size_t)c * NSP + n4);
    }
    CP_COMMIT();

    // q(0) -> registers (2 float4 per thread covers 64x64 tile)
    const int qu0 = tid, qu1 = tid + 512;
    float4 rq0 = *(const float4*)(qTb + (qu0 >> 4) * CQ + ((qu0 & 15) << 2));
    float4 rq1 = *(const float4*)(qTb + (qu1 >> 4) * CQ + ((qu1 & 15) << 2));

    float oacc[2][8][4];
#pragma unroll
    for (int a = 0; a < 2; a++)
#pragma unroll
        for (int j = 0; j < 8; j++)
#pragma unroll
            for (int e = 0; e < 4; e++) oacc[a][j][e] = 0.f;

    for (int nt = 0; nt < 64; ++nt) {
        const int st = nt & 1;
        __syncthreads();   // qs, ss, vs[st^1] free (prev GEMM1/epi/GEMM2 done)

        // store q(nt) from registers
        *(float4*)&qs[qu0 >> 4][(qu0 & 15) << 2] = rq0;
        *(float4*)&qs[qu1 >> 4][(qu1 & 15) << 2] = rq1;

        if (nt < 63) {     // prefetch V(nt+1) into the free buffer
            const float* vg = Vb + (nt + 1) * 64;
            const uint32_t vbase = sb + (uint32_t)(ATT_VS + (st ^ 1) * ATT_VSZ) * 4;
#pragma unroll
            for (int u = tid; u < 4096; u += 512) {
                int c = u >> 4, n4 = (u & 15) << 2;
                cp16(vbase + (uint32_t)(c * 68 + n4) * 4, vg + (size_t)c * NSP + n4);
            }
            CP_COMMIT();
            CP_WAIT1();    // V(nt) resident
        } else {
            CP_WAIT0();
        }
        __syncthreads();   // qs + vs[st] visible to all

        // prefetch q(nt+1) -> registers (covered by GEMM1+GEMM2)
        if (nt < 63) {
            const float* qg = qTb + (size_t)(nt + 1) * 64 * CQ;
            rq0 = *(const float4*)(qg + (qu0 >> 4) * CQ + ((qu0 & 15) << 2));
            rq1 = *(const float4*)(qg + (qu1 >> 4) * CQ + ((qu1 & 15) << 2));
        }

        // ---- GEMM1: S = q . k ----
        float sacc[4][4];
#pragma unroll
        for (int j = 0; j < 4; j++)
#pragma unroll
            for (int e = 0; e < 4; e++) sacc[j][e] = 0.f;

#pragma unroll
        for (int kk = 0; kk < 64; kk += 8) {
            unsigned a[4];
            a[0] = __float_as_uint(qs[i1 + g][kk + t4]);
            a[1] = __float_as_uint(qs[i1 + g + 8][kk + t4]);
            a[2] = __float_as_uint(qs[i1 + g][kk + t4 + 4]);
            a[3] = __float_as_uint(qs[i1 + g + 8][kk + t4 + 4]);
#pragma unroll
            for (int jt = 0; jt < 4; jt++) {
                unsigned b0 = __float_as_uint(ks[j1 + jt * 8 + g][kk + t4]);
                unsigned b1 = __float_as_uint(ks[j1 + jt * 8 + g][kk + t4 + 4]);
                mma8(sacc[jt], a, b0, b1);
            }
        }

        // ---- elu/N epilogue -> ss[m][n] ----
#pragma unroll
        for (int jt = 0; jt < 4; jt++) {
            const int ma  = j1 + jt * 8 + 2 * t4;
            const int ilo = i1 + g, ihi = ilo + 8;
            ss[ma    ][ilo] = elu_scale(sacc[jt][0]);
            ss[ma + 1][ilo] = elu_scale(sacc[jt][1]);
            ss[ma    ][ihi] = elu_scale(sacc[jt][2]);
            ss[ma + 1][ihi] = elu_scale(sacc[jt][3]);
        }
        __syncthreads();   // ss visible

        // ---- GEMM2: O += V' . S ----
        const float (*vs)[68] = (const float(*)[68])(sm + ATT_VS + st * ATT_VSZ);
#pragma unroll
        for (int kk = 0; kk < 64; kk += 8) {
            unsigned a[2][4];
#pragma unroll
            for (int mt = 0; mt < 2; mt++) {
                const int cb = c2 + mt * 16;
                a[mt][0] = __float_as_uint(vs[cb + g][kk + t4]);
                a[mt][1] = __float_as_uint(vs[cb + g + 8][kk + t4]);
                a[mt][2] = __float_as_uint(vs[cb + g][kk + t4 + 4]);
                a[mt][3] = __float_as_uint(vs[cb + g + 8][kk + t4 + 4]);
            }
#pragma unroll
            for (int jt = 0; jt < 8; jt++) {
                unsigned b0 = __float_as_uint(ss[j2 + jt * 8 + g][kk + t4]);
                unsigned b1 = __float_as_uint(ss[j2 + jt * 8 + g][kk + t4 + 4]);
                mma8(oacc[0][jt], a[0], b0, b1);
                mma8(oacc[1][jt], a[1], b0, b1);
            }
        }
    }

    // ---- final epilogue: add gamma bias, write output ----
#pragma unroll
    for (int mt = 0; mt < 2; mt++) {
        const int olo = c2 + mt * 16 + g;
        const int ohi = olo + 8;
        const float blo = __ldg(bg + olo);
        const float bhi = __ldg(bg + ohi);
#pragma unroll
        for (int jt = 0; jt < 8; jt++) {
            const int m_ = m0 + j2 + jt * 8 + 2 * t4;
            float2 v0 = make_float2(oacc[mt][jt][0] + blo, oacc[mt][jt][1] + blo);
            float2 v1 = make_float2(oacc[mt][jt][2] + bhi, oacc[mt][jt][3] + bhi);
            *(float2*)(out + ((size_t)b * CC + olo) * NSP + m_) = v0;
            *(float2*)(out + ((size_t)b * CC + ohi) * NSP + m_) = v1;
        }
    }
}

// ---------------------------------------------------------------------------
// Launch
// ---------------------------------------------------------------------------
extern "C" void kernel_launch(void* const* d_in, const int* in_sizes, int n_in,
                              void* d_out, int out_size) {
    const float* x  = (const float*)d_in[0];
    const float* Wq = (const float*)d_in[1];
    const float* bq = (const float*)d_in[2];
    const float* Wk = (const float*)d_in[3];
    const float* bk = (const float*)d_in[4];
    const float* Wv = (const float*)d_in[5];
    const float* bv = (const float*)d_in[6];
    const float* Wg = (const float*)d_in[7];
    const float* bg = (const float*)d_in[8];
    float* out = (float*)d_out;

    cudaFuncSetAttribute(attn_kernel, cudaFuncAttributeMaxDynamicSharedMemorySize, ATT_BYTES);

    prep_weights<<<96, 256>>>(Wq, bq, Wk, bk, Wv, bv, Wg);
    qkv_kernel<<<dim3(3, 32, 8), 256>>>(x);
    attn_kernel<<<dim3(32, 8), 512, ATT_BYTES>>>(out, bg);
}

// round 16
// speedup vs baseline: 1.2566x; 1.0009x over previous
#include <cuda_runtime.h>
#include <cstdint>
#include <cstddef>

// Problem shape (fixed by the dataset)
#define BB   8
#define CC   256
#define CQ   64
#define NSP  4096   // H*W = 64*64

// ---------------------------------------------------------------------------
// Scratch (static __device__ arrays -- no allocation allowed)
// ---------------------------------------------------------------------------
__device__ __align__(16) float g_Wall[384 * 256];            // [Wq;Wk;Wg@Wv]
__device__ __align__(16) float g_ball[384];                  // [bq;bk;Wg@bv]
__device__ __align__(16) float g_qT[BB * NSP * CQ];          // [b][i][c]  tf32-rounded
__device__ __align__(16) float g_kT[BB * NSP * CQ];          // [b][j][c]  tf32-rounded
__device__ __align__(16) float g_Vp[BB * CC * NSP];          // [b][o][n]  tf32-rounded

// ---------------------------------------------------------------------------
// Helpers
// ---------------------------------------------------------------------------
__device__ __forceinline__ float rna_tf32(float x) {
    unsigned y;
    asm("cvt.rna.tf32.f32 %0, %1;" : "=r"(y) : "f"(x));
    return __uint_as_float(y);
}

__device__ __forceinline__ uint32_t smem_u32(const void* p) {
    uint32_t a;
    asm("{ .reg .u64 t; cvta.to.shared.u64 t, %1; cvt.u32.u64 %0, t; }" : "=r"(a) : "l"(p));
    return a;
}

__device__ __forceinline__ void mma8(float* d, const unsigned* a, unsigned b0, unsigned b1) {
    asm volatile(
        "mma.sync.aligned.m16n8k8.row.col.f32.tf32.tf32.f32 "
        "{%0,%1,%2,%3}, {%4,%5,%6,%7}, {%8,%9}, {%0,%1,%2,%3};"
        : "+f"(d[0]), "+f"(d[1]), "+f"(d[2]), "+f"(d[3])
        : "r"(a[0]), "r"(a[1]), "r"(a[2]), "r"(a[3]), "r"(b0), "r"(b1));
}

__device__ __forceinline__ void cp16(uint32_t dst, const void* src) {
    asm volatile("cp.async.cg.shared.global [%0], [%1], 16;" :: "r"(dst), "l"(src) : "memory");
}
#define CP_COMMIT() asm volatile("cp.async.commit_group;" ::: "memory")
#define CP_WAIT1()  asm volatile("cp.async.wait_group 1;" ::: "memory")
#define CP_WAIT0()  asm volatile("cp.async.wait_group 0;" ::: "memory")

// ---------------------------------------------------------------------------
// Kernel 0: fold gamma into value conv. Blocks 0..31: round/copy Wq,Wk rows
// (4 rows each). Blocks 32..95: Wg@Wv, 4 output rows per block (Wv reuse x4).
// ---------------------------------------------------------------------------
__global__ __launch_bounds__(256) void prep_weights(
        const float* __restrict__ Wq, const float* __restrict__ bq,
        const float* __restrict__ Wk, const float* __restrict__ bk,
        const float* __restrict__ Wv, const float* __restrict__ bv,
        const float* __restrict__ Wg) {
    const int blk = blockIdx.x;
    const int t = threadIdx.x;
    if (blk < 32) {
#pragma unroll
        for (int rr = 0; rr < 4; rr++) {
            const int r = blk * 4 + rr;   // 0..127
            const float src = (r < 64) ? Wq[r * 256 + t] : Wk[(r - 64) * 256 + t];
            g_Wall[r * 256 + t] = rna_tf32(src);
        }
        if (t < 4) {
            const int r = blk * 4 + t;
            g_ball[r] = (r < 64) ? bq[r] : bk[r - 64];
        }
    } else {
        const int o0 = (blk - 32) * 4;    // 0..252
        __shared__ float wg[4][256];
#pragma unroll
        for (int rr = 0; rr < 4; rr++) wg[rr][t] = Wg[(o0 + rr) * 256 + t];
        __syncthreads();
        float acc0 = 0.f, acc1 = 0.f, acc2 = 0.f, acc3 = 0.f;
#pragma unroll 4
        for (int c = 0; c < 256; c++) {
            const float wv = Wv[c * 256 + t];
            acc0 = fmaf(wg[0][c], wv, acc0);
            acc1 = fmaf(wg[1][c], wv, acc1);
            acc2 = fmaf(wg[2][c], wv, acc2);
            acc3 = fmaf(wg[3][c], wv, acc3);
        }
        g_Wall[(128 + o0 + 0) * 256 + t] = rna_tf32(acc0);
        g_Wall[(128 + o0 + 1) * 256 + t] = rna_tf32(acc1);
        g_Wall[(128 + o0 + 2) * 256 + t] = rna_tf32(acc2);
        g_Wall[(128 + o0 + 3) * 256 + t] = rna_tf32(acc3);
        if (t < 4) {
            float bacc = 0.f;
            for (int c = 0; c < 256; c++) bacc = fmaf(wg[t][c], bv[c], bacc);
            g_ball[128 + o0 + t] = bacc;
        }
    }
}

// ---------------------------------------------------------------------------
// Kernel 1: qkv projection (mma.sync tf32 -- known good from R2)
// ---------------------------------------------------------------------------
__device__ __forceinline__ void store_qkv(int b, int r, int i, float v) {
    v = rna_tf32(v + g_ball[r]);
    if (r < 64)        g_qT[((size_t)b * NSP + i) * CQ + r] = v;
    else if (r < 128)  g_kT[((size_t)b * NSP + i) * CQ + (r - 64)] = v;
    else               g_Vp[((size_t)b * CC + (r - 128)) * NSP + i] = v;
}

__global__ __launch_bounds__(256) void qkv_kernel(const float* __restrict__ x) {
    __shared__ float xs[32][136];
    __shared__ float ws[128][36];
    const int b  = blockIdx.z;
    const int r0 = blockIdx.x * 128;
    const int i0 = blockIdx.y * 128;
    const int tid = threadIdx.x;
    const int w = tid >> 5, l = tid & 31, g = l >> 2, t = l & 3;
    const int rw = (w & 3) * 32;
    const int iw = (w >> 2) * 64;

    float oacc[2][8][4];
#pragma unroll
    for (int a = 0; a < 2; a++)
#pragma unroll
        for (int j = 0; j < 8; j++)
#pragma unroll
            for (int e = 0; e < 4; e++) oacc[a][j][e] = 0.f;

    const float* xb = x + (size_t)b * CC * NSP;

    for (int kc = 0; kc < 256; kc += 32) {
        __syncthreads();
#pragma unroll
        for (int u = tid; u < 1024; u += 256) {
            int c = u >> 5, i4 = (u & 31) * 4;
            float4 v = *(const float4*)(xb + (size_t)(kc + c) * NSP + i0 + i4);
            xs[c][i4 + 0] = rna_tf32(v.x);
            xs[c][i4 + 1] = rna_tf32(v.y);
            xs[c][i4 + 2] = rna_tf32(v.z);
            xs[c][i4 + 3] = rna_tf32(v.w);
        }
#pragma unroll
        for (int u = tid; u < 1024; u += 256) {
            int r = u >> 3, c4 = (u & 7) * 4;
            *(float4*)&ws[r][c4] = *(const float4*)(g_Wall + (r0 + r) * 256 + kc + c4);
        }
        __syncthreads();
#pragma unroll
        for (int kk = 0; kk < 32; kk += 8) {
            unsigned a[2][4];
#pragma unroll
            for (int mt = 0; mt < 2; mt++) {
                const int rb = rw + mt * 16;
                a[mt][0] = __float_as_uint(ws[rb + g][kk + t]);
                a[mt][1] = __float_as_uint(ws[rb + g + 8][kk + t]);
                a[mt][2] = __float_as_uint(ws[rb + g][kk + t + 4]);
                a[mt][3] = __float_as_uint(ws[rb + g + 8][kk + t + 4]);
            }
#pragma unroll
            for (int jt = 0; jt < 8; jt++) {
                unsigned b0 = __float_as_uint(xs[kk + t][iw + jt * 8 + g]);
                unsigned b1 = __float_as_uint(xs[kk + t + 4][iw + jt * 8 + g]);
                mma8(oacc[0][jt], a[0], b0, b1);
                mma8(oacc[1][jt], a[1], b0, b1);
            }
        }
    }

#pragma unroll
    for (int mt = 0; mt < 2; mt++) {
#pragma unroll
        for (int jt = 0; jt < 8; jt++) {
            const int rlo = r0 + rw + mt * 16 + g;
            const int rhi = rlo + 8;
            const int ib  = i0 + iw + jt * 8 + 2 * t;
            store_qkv(b, rlo, ib,     oacc[mt][jt][0]);
            store_qkv(b, rlo, ib + 1, oacc[mt][jt][1]);
            store_qkv(b, rhi, ib,     oacc[mt][jt][2]);
            store_qkv(b, rhi, ib + 1, oacc[mt][jt][3]);
        }
    }
}

// ---------------------------------------------------------------------------
// Kernel 2: fused attention (mma.sync tf32), cp.async-pipelined.
// Per CTA: batch b, 128 m-cols, all 256 c. Loop n-tiles of 64:
//   GEMM1: S[64n x 128m] = q.k ; elu/N -> ss[m][n] (transposed, pitch 68)
//   GEMM2: O[256c x 128m] += Vp[c][n] . ss
// V tiles double-buffered via cp.async; q tiles prefetched through registers;
// K tile CTA-resident. 3 barriers/iter; elu via MUFU (__expf).
// ---------------------------------------------------------------------------
#define ATT_KS   0                         // 128 x 68
#define ATT_QS   (128 * 68)                // 64 x 68
#define ATT_VS   (ATT_QS + 64 * 68)        // 2 x (256 x 68)
#define ATT_VSZ  (256 * 68)
#define ATT_SS   (ATT_VS + 2 * ATT_VSZ)    // 128 x 68
#define ATT_FLOATS (ATT_SS + 128 * 68)     // 56576
#define ATT_BYTES  (ATT_FLOATS * 4)        // 226304 <= 232448

__device__ __forceinline__ float elu_scale(float v) {
    float e = (v > 0.f) ? v : (__expf(v) - 1.0f);   // MUFU path, abs err ~1e-7
    return rna_tf32(e * (1.0f / 4096.0f));
}

__global__ __launch_bounds__(512, 1) void attn_kernel(float* __restrict__ out,
                                                      const float* __restrict__ bg) {
    extern __shared__ float sm[];
    float (*ks)[68] = (float(*)[68])(sm + ATT_KS);
    float (*qs)[68] = (float(*)[68])(sm + ATT_QS);
    float (*ss)[68] = (float(*)[68])(sm + ATT_SS);
    const uint32_t sb = smem_u32(sm);

    const int b  = blockIdx.y;
    const int m0 = blockIdx.x * 128;
    const int tid = threadIdx.x;
    const int w = tid >> 5, l = tid & 31, g = l >> 2, t4 = l & 3;
    // GEMM1 warp tile: 16(i=n) x 32(j=m); GEMM2 warp tile: 32(c) x 64(m)
    const int i1 = (w & 3) * 16;
    const int j1 = (w >> 2) * 32;
    const int c2 = (w & 7) * 32;
    const int j2 = (w >> 3) * 64;

    const float* kTb = g_kT + ((size_t)b * NSP + m0) * CQ;
    const float* qTb = g_qT + (size_t)b * NSP * CQ;
    const float* Vb  = g_Vp + (size_t)b * CC * NSP;

    // ---- prologue: cp.async K tile + V stage 0 (one group) ----
#pragma unroll
    for (int u = tid; u < 2048; u += 512) {          // ks 128 x 16 chunks
        int j = u >> 4, c4 = (u & 15) << 2;
        cp16(sb + (uint32_t)(ATT_KS + j * 68 + c4) * 4, kTb + j * CQ + c4);
    }
#pragma unroll
    for (int u = tid; u < 4096; u += 512) {          // vs0 256 x 16 chunks
        int c = u >> 4, n4 = (u & 15) << 2;
        cp16(sb + (uint32_t)(ATT_VS + c * 68 + n4) * 4, Vb + (size_t)c * NSP + n4);
    }
    CP_COMMIT();

    // q(0) -> registers (2 float4 per thread covers 64x64 tile)
    const int qu0 = tid, qu1 = tid + 512;
    float4 rq0 = *(const float4*)(qTb + (qu0 >> 4) * CQ + ((qu0 & 15) << 2));
    float4 rq1 = *(const float4*)(qTb + (qu1 >> 4) * CQ + ((qu1 & 15) << 2));

    float oacc[2][8][4];
#pragma unroll
    for (int a = 0; a < 2; a++)
#pragma unroll
        for (int j = 0; j < 8; j++)
#pragma unroll
            for (int e = 0; e < 4; e++) oacc[a][j][e] = 0.f;

    for (int nt = 0; nt < 64; ++nt) {
        const int st = nt & 1;
        __syncthreads();   // qs, ss, vs[st^1] free (prev GEMM1/epi/GEMM2 done)

        // store q(nt) from registers
        *(float4*)&qs[qu0 >> 4][(qu0 & 15) << 2] = rq0;
        *(float4*)&qs[qu1 >> 4][(qu1 & 15) << 2] = rq1;

        if (nt < 63) {     // prefetch V(nt+1) into the free buffer
            const float* vg = Vb + (nt + 1) * 64;
            const uint32_t vbase = sb + (uint32_t)(ATT_VS + (st ^ 1) * ATT_VSZ) * 4;
#pragma unroll
            for (int u = tid; u < 4096; u += 512) {
                int c = u >> 4, n4 = (u & 15) << 2;
                cp16(vbase + (uint32_t)(c * 68 + n4) * 4, vg + (size_t)c * NSP + n4);
            }
            CP_COMMIT();
            CP_WAIT1();    // V(nt) resident
        } else {
            CP_WAIT0();
        }
        __syncthreads();   // qs + vs[st] visible to all

        // prefetch q(nt+1) -> registers (covered by GEMM1+GEMM2)
        if (nt < 63) {
            const float* qg = qTb + (size_t)(nt + 1) * 64 * CQ;
            rq0 = *(const float4*)(qg + (qu0 >> 4) * CQ + ((qu0 & 15) << 2));
            rq1 = *(const float4*)(qg + (qu1 >> 4) * CQ + ((qu1 & 15) << 2));
        }

        // ---- GEMM1: S = q . k ----
        float sacc[4][4];
#pragma unroll
        for (int j = 0; j < 4; j++)
#pragma unroll
            for (int e = 0; e < 4; e++) sacc[j][e] = 0.f;

#pragma unroll
        for (int kk = 0; kk < 64; kk += 8) {
            unsigned a[4];
            a[0] = __float_as_uint(qs[i1 + g][kk + t4]);
            a[1] = __float_as_uint(qs[i1 + g + 8][kk + t4]);
            a[2] = __float_as_uint(qs[i1 + g][kk + t4 + 4]);
            a[3] = __float_as_uint(qs[i1 + g + 8][kk + t4 + 4]);
#pragma unroll
            for (int jt = 0; jt < 4; jt++) {
                unsigned b0 = __float_as_uint(ks[j1 + jt * 8 + g][kk + t4]);
                unsigned b1 = __float_as_uint(ks[j1 + jt * 8 + g][kk + t4 + 4]);
                mma8(sacc[jt], a, b0, b1);
            }
        }

        // ---- elu/N epilogue -> ss[m][n] ----
#pragma unroll
        for (int jt = 0; jt < 4; jt++) {
            const int ma  = j1 + jt * 8 + 2 * t4;
            const int ilo = i1 + g, ihi = ilo + 8;
            ss[ma    ][ilo] = elu_scale(sacc[jt][0]);
            ss[ma + 1][ilo] = elu_scale(sacc[jt][1]);
            ss[ma    ][ihi] = elu_scale(sacc[jt][2]);
            ss[ma + 1][ihi] = elu_scale(sacc[jt][3]);
        }
        __syncthreads();   // ss visible

        // ---- GEMM2: O += V' . S ----
        const float (*vs)[68] = (const float(*)[68])(sm + ATT_VS + st * ATT_VSZ);
#pragma unroll
        for (int kk = 0; kk < 64; kk += 8) {
            unsigned a[2][4];
#pragma unroll
            for (int mt = 0; mt < 2; mt++) {
                const int cb = c2 + mt * 16;
                a[mt][0] = __float_as_uint(vs[cb + g][kk + t4]);
                a[mt][1] = __float_as_uint(vs[cb + g + 8][kk + t4]);
                a[mt][2] = __float_as_uint(vs[cb + g][kk + t4 + 4]);
                a[mt][3] = __float_as_uint(vs[cb + g + 8][kk + t4 + 4]);
            }
#pragma unroll
            for (int jt = 0; jt < 8; jt++) {
                unsigned b0 = __float_as_uint(ss[j2 + jt * 8 + g][kk + t4]);
                unsigned b1 = __float_as_uint(ss[j2 + jt * 8 + g][kk + t4 + 4]);
                mma8(oacc[0][jt], a[0], b0, b1);
                mma8(oacc[1][jt], a[1], b0, b1);
            }
        }
    }

    // ---- final epilogue: add gamma bias, write output ----
#pragma unroll
    for (int mt = 0; mt < 2; mt++) {
        const int olo = c2 + mt * 16 + g;
        const int ohi = olo + 8;
        const float blo = __ldg(bg + olo);
        const float bhi = __ldg(bg + ohi);
#pragma unroll
        for (int jt = 0; jt < 8; jt++) {
            const int m_ = m0 + j2 + jt * 8 + 2 * t4;
            float2 v0 = make_float2(oacc[mt][jt][0] + blo, oacc[mt][jt][1] + blo);
            float2 v1 = make_float2(oacc[mt][jt][2] + bhi, oacc[mt][jt][3] + bhi);
            *(float2*)(out + ((size_t)b * CC + olo) * NSP + m_) = v0;
            *(float2*)(out + ((size_t)b * CC + ohi) * NSP + m_) = v1;
        }
    }
}

// ---------------------------------------------------------------------------
// Launch
// ---------------------------------------------------------------------------
extern "C" void kernel_launch(void* const* d_in, const int* in_sizes, int n_in,
                              void* d_out, int out_size) {
    const float* x  = (const float*)d_in[0];
    const float* Wq = (const float*)d_in[1];
    const float* bq = (const float*)d_in[2];
    const float* Wk = (const float*)d_in[3];
    const float* bk = (const float*)d_in[4];
    const float* Wv = (const float*)d_in[5];
    const float* bv = (const float*)d_in[6];
    const float* Wg = (const float*)d_in[7];
    const float* bg = (const float*)d_in[8];
    float* out = (float*)d_out;

    cudaFuncSetAttribute(attn_kernel, cudaFuncAttributeMaxDynamicSharedMemorySize, ATT_BYTES);

    prep_weights<<<96, 256>>>(Wq, bq, Wk, bk, Wv, bv, Wg);
    qkv_kernel<<<dim3(3, 32, 8), 256>>>(x);
    attn_kernel<<<dim3(32, 8), 512, ATT_BYTES>>>(out, bg);
}